// round 13
// baseline (speedup 1.0000x reference)
#include <cuda_runtime.h>
#include <cuda_bf16.h>
#include <cstdint>

#define BSZ  16
#define CCH  64
#define LSEQ 36864
#define DM   16
#define DI   32
#define DS   16
#define NSEQ 64
#define COUT 48

#define NCH  72
#define CSZ  512           // LSEQ / NCH
#define WARM 32
#define TILE 16
#define WPB  4
#define NB1  288           // LSEQ / 128

// ---------------- packed f32x2 helpers (sm_103a; ptxas won't auto-fuse) ------
typedef unsigned long long f2;
__device__ __forceinline__ f2 pk2(float lo, float hi) {
    f2 r; asm("mov.b64 %0,{%1,%2};" : "=l"(r) : "f"(lo), "f"(hi)); return r;
}
__device__ __forceinline__ void up2(f2 v, float& a, float& b) {
    asm("mov.b64 {%0,%1},%2;" : "=f"(a), "=f"(b) : "l"(v));
}
__device__ __forceinline__ f2 fma2(f2 a, f2 b, f2 c) {
    f2 d; asm("fma.rn.f32x2 %0,%1,%2,%3;" : "=l"(d) : "l"(a), "l"(b), "l"(c)); return d;
}
__device__ __forceinline__ f2 mul2(f2 a, f2 b) {
    f2 d; asm("mul.rn.f32x2 %0,%1,%2;" : "=l"(d) : "l"(a), "l"(b)); return d;
}
__device__ __forceinline__ f2 add2(f2 a, f2 b) {
    f2 d; asm("add.rn.f32x2 %0,%1,%2;" : "=l"(d) : "l"(a), "l"(b)); return d;
}
__device__ __forceinline__ float hadd2(f2 v) {
    float a, b; up2(v, a, b); return a + b;
}

// ---------------- scratch (device globals; no runtime allocation) ------------
__device__ float         g_un[(size_t)NSEQ * LSEQ * DM];
__device__ __nv_bfloat16 g_q [(size_t)NSEQ * LSEQ * DI];
__device__ float g_unpart[BSZ * NB1 * CCH];
__device__ float g_qpart [NSEQ * NCH * DI];
__device__ float g_unsum [NSEQ * DM];
__device__ float g_gate  [NSEQ * DI];
__device__ float g_A [DI * DS];
__device__ float g_a0[DI];
__device__ int   g_struct;

__device__ __forceinline__ float sigf(float v) {
    return __fdividef(1.f, 1.f + __expf(-v));
}

// ---------------- prep: A = -exp(A_log), detect power structure --------------
__global__ void k_prep(const float* __restrict__ A_log) {
    int d = threadIdx.x;  // 32 threads
    float a[DS];
#pragma unroll
    for (int n = 0; n < DS; n++) {
        a[n] = -expf(A_log[d * DS + n]);
        g_A[d * DS + n] = a[n];
    }
    g_a0[d] = a[0];
    int good = 1;
#pragma unroll
    for (int n = 0; n < DS; n++) {
        float r = a[0] * (float)(n + 1);
        if (fabsf(a[n] - r) > 1e-4f * fmaxf(1.f, fabsf(r))) good = 0;
    }
    int allok = __syncthreads_and(good);
    if (d == 0) g_struct = allok;
}

// ---------------- pass 1: layernorm + regroup + skip partial sums ------------
__global__ void __launch_bounds__(128) k_ln1(const float* __restrict__ x,
                                             const float* __restrict__ ng,
                                             const float* __restrict__ nb) {
    __shared__ float tile[CCH][129];
    __shared__ float sM[128], sR[128];
    __shared__ float sG[CCH], sB[CCH];
    int t = threadIdx.x, blk = blockIdx.x, b = blockIdx.y;
    if (t < CCH) { sG[t] = ng[t]; sB[t] = nb[t]; }

    const float* xb = x + (size_t)b * CCH * LSEQ + (size_t)blk * 128;
    float sum = 0.f, sq = 0.f;
#pragma unroll 4
    for (int c = 0; c < CCH; c++) {
        float v = xb[(size_t)c * LSEQ + t];
        tile[c][t] = v;
        sum += v;
        sq = fmaf(v, v, sq);
    }
    float mean = sum * (1.f / 64.f);
    float var  = sq * (1.f / 64.f) - mean * mean;
    sM[t] = mean;
    sR[t] = rsqrtf(var + 1e-5f);
    __syncthreads();

#pragma unroll
    for (int g = 0; g < 4; g++) {
        float* ob = g_un + ((size_t)(g * 16 + b) * LSEQ + (size_t)blk * 128) * DM;
#pragma unroll 4
        for (int rep = 0; rep < 16; rep++) {
            int idx = rep * 128 + t;
            int l = idx >> 4, j = idx & 15;
            int c = g * 16 + j;
            ob[idx] = (tile[c][l] - sM[l]) * sR[l] * sG[c] + sB[c];
        }
    }
    if (t < CCH) {
        float a = 0.f;
#pragma unroll 4
        for (int l = 0; l < 128; l++) a += (tile[t][l] - sM[l]) * sR[l];
        g_unpart[((size_t)b * NB1 + blk) * CCH + t] = a * sG[t] + 128.f * sB[t];
    }
}

// ---------------- reduce skip-path partials ----------------------------------
__global__ void k_red1() {
    int id = blockIdx.x * 256 + threadIdx.x;
    if (id >= NSEQ * DM) return;
    int s = id >> 4, j = id & 15;
    int b = s & 15, g = s >> 4;
    float a = 0.f;
    for (int blk = 0; blk < NB1; blk++)
        a += g_unpart[((size_t)b * NB1 + blk) * CCH + g * 16 + j];
    g_unsum[id] = a;
}

// ---------------- pass 2: mamba (in-proj + conv + xproj + selective scan) ----
__global__ void __launch_bounds__(128, 4) k_scan(
    const float* __restrict__ in_w,     const float* __restrict__ conv_w,
    const float* __restrict__ conv_b,   const float* __restrict__ xproj_w,
    const float* __restrict__ dtproj_w, const float* __restrict__ dtproj_b,
    const float* __restrict__ Dp)
{
    __shared__ __align__(16) float w0s[32];               // xproj_w row 0
    __shared__ __align__(16) float su  [WPB][256];        // u tile [t][k]
    __shared__ __align__(16) float sAct[WPB][TILE][40];   // act [t][d]
    __shared__ __align__(16) float sZs [WPB][TILE][40];   // silu(z) [t][d]
    __shared__ __align__(16) float sBC [WPB][TILE][40];   // [0..15]=B [16..31]=C [32]=dt

    int tid = threadIdx.x, wid = tid >> 5, lane = tid & 31;
    if (tid < 32) w0s[tid] = xproj_w[tid];
    __syncthreads();

    int job = blockIdx.x * WPB + wid;          // 0..4607
    int s = job / NCH, ch = job - s * NCH;
    int qstart = ch * CSZ;
    int start  = (qstart >= WARM) ? (qstart - WARM) : 0;
    int nsteps = qstart + CSZ - start;
    int woff   = qstart - start;
    const float* uBase = g_un + ((size_t)s * LSEQ + start) * DM;
    __nv_bfloat16* qBase = g_q + ((size_t)s * LSEQ + start) * DI;

    // per-lane register-resident weights (packed pairs)
    f2 wx2[8], wz2[8], wc2[16];
    {
        const ulonglong2* wxp = (const ulonglong2*)(in_w + lane * 16);
        const ulonglong2* wzp = (const ulonglong2*)(in_w + (32 + lane) * 16);
        const ulonglong2* wcp = (const ulonglong2*)(xproj_w + 32 + lane * 32);
#pragma unroll
        for (int i = 0; i < 4; i++) {
            ulonglong2 a = wxp[i]; wx2[2 * i] = a.x; wx2[2 * i + 1] = a.y;
            ulonglong2 b = wzp[i]; wz2[2 * i] = b.x; wz2[2 * i + 1] = b.y;
        }
#pragma unroll
        for (int i = 0; i < 8; i++) {
            ulonglong2 c = wcp[i]; wc2[2 * i] = c.x; wc2[2 * i + 1] = c.y;
        }
    }
    float4 cwv = *(const float4*)(conv_w + lane * 4);
    float cb  = conv_b[lane];
    float dtw = dtproj_w[lane], dtb = dtproj_b[lane];
    float Dd  = Dp[lane], a0 = g_a0[lane];
    int structured = g_struct;

    f2 h2[8];
#pragma unroll
    for (int k = 0; k < 8; k++) h2[k] = 0ULL;
    float xm1 = 0.f, xm2 = 0.f, xm3 = 0.f;
    float qsum = 0.f;

    for (int tb = 0; tb < nsteps; tb += TILE) {
        // ---- A0: stage u tile ----
        {
            const float4* gsrc = (const float4*)(uBase + (size_t)tb * DM);
            float4* sdst = (float4*)su[wid];
            sdst[lane]      = gsrc[lane];
            sdst[lane + 32] = gsrc[lane + 32];
        }
        __syncwarp();

        // ---- A1: in-proj (packed k-pairs) + depthwise conv + silu (lane=d) --
#pragma unroll
        for (int t = 0; t < TILE; t++) {
            const ulonglong2* up = (const ulonglong2*)&su[wid][t * 16];
            ulonglong2 u0 = up[0], u1 = up[1], u2v = up[2], u3v = up[3];
            f2 ax2 = 0ULL, az2 = 0ULL;
            ax2 = fma2(u0.x, wx2[0], ax2);  az2 = fma2(u0.x, wz2[0], az2);
            ax2 = fma2(u0.y, wx2[1], ax2);  az2 = fma2(u0.y, wz2[1], az2);
            ax2 = fma2(u1.x, wx2[2], ax2);  az2 = fma2(u1.x, wz2[2], az2);
            ax2 = fma2(u1.y, wx2[3], ax2);  az2 = fma2(u1.y, wz2[3], az2);
            ax2 = fma2(u2v.x, wx2[4], ax2); az2 = fma2(u2v.x, wz2[4], az2);
            ax2 = fma2(u2v.y, wx2[5], ax2); az2 = fma2(u2v.y, wz2[5], az2);
            ax2 = fma2(u3v.x, wx2[6], ax2); az2 = fma2(u3v.x, wz2[6], az2);
            ax2 = fma2(u3v.y, wx2[7], ax2); az2 = fma2(u3v.y, wz2[7], az2);
            float ax = hadd2(ax2), az = hadd2(az2);
            float acc = cb;
            acc = fmaf(cwv.x, xm3, acc);
            acc = fmaf(cwv.y, xm2, acc);
            acc = fmaf(cwv.z, xm1, acc);
            acc = fmaf(cwv.w, ax,  acc);
            xm3 = xm2; xm2 = xm1; xm1 = ax;
            sAct[wid][t][lane] = acc * sigf(acc);
            sZs [wid][t][lane] = az * sigf(az);
        }
        __syncwarp();

        // ---- A3: x-projection (lane = output column, packed d-pairs) --------
        {
#pragma unroll
            for (int t = 0; t < TILE; t++) {
                const ulonglong2* ap = (const ulonglong2*)&sAct[wid][t][0];
                f2 o2 = 0ULL;
#pragma unroll
                for (int i = 0; i < 8; i++) {
                    ulonglong2 a = ap[i];
                    o2 = fma2(a.x, wc2[2 * i], o2);
                    o2 = fma2(a.y, wc2[2 * i + 1], o2);
                }
                sBC[wid][t][lane] = hadd2(o2);
            }
            // dt_raw row: lanes 0..15 each handle one timestep
            if (lane < TILE) {
                const ulonglong2* ap = (const ulonglong2*)&sAct[wid][lane][0];
                const ulonglong2* wp = (const ulonglong2*)w0s;
                f2 s2 = 0ULL;
#pragma unroll
                for (int i = 0; i < 8; i++) {
                    ulonglong2 a = ap[i];
                    ulonglong2 w = wp[i];
                    s2 = fma2(a.x, w.x, s2);
                    s2 = fma2(a.y, w.y, s2);
                }
                sBC[wid][lane][32] = hadd2(s2);
            }
        }
        __syncwarp();

        // ---- B: selective scan (lane = d, packed n-pairs) -------------------
        if (structured) {
#pragma unroll
            for (int tt = 0; tt < TILE; tt++) {
                float dtr = sBC[wid][tt][32];
                float act = sAct[wid][tt][lane];
                float zsv = sZs[wid][tt][lane];
                float pre = fmaf(dtr, dtw, dtb);
                float dt = (pre > 20.f) ? pre : __logf(1.f + __expf(pre));
                float bx = dt * act;
                f2 bx2 = pk2(bx, bx);
                float p = __expf(dt * a0);
                float pq = p * p;
                f2 Q = pk2(pq, pq);
                f2 pw = pk2(p, pq);
                const ulonglong2* bp = (const ulonglong2*)&sBC[wid][tt][0];
                ulonglong2 Bq0 = bp[0], Bq1 = bp[1], Bq2 = bp[2], Bq3 = bp[3];
                ulonglong2 Cq0 = bp[4], Cq1 = bp[5], Cq2 = bp[6], Cq3 = bp[7];
                f2 Bv[8] = {Bq0.x, Bq0.y, Bq1.x, Bq1.y, Bq2.x, Bq2.y, Bq3.x, Bq3.y};
                f2 Cv[8] = {Cq0.x, Cq0.y, Cq1.x, Cq1.y, Cq2.x, Cq2.y, Cq3.x, Cq3.y};
                f2 y2 = 0ULL;
#pragma unroll
                for (int k = 0; k < 8; k++) {
                    h2[k] = fma2(pw, h2[k], mul2(bx2, Bv[k]));
                    y2 = fma2(h2[k], Cv[k], y2);
                    pw = mul2(pw, Q);
                }
                int t = tb + tt;
                if (t >= woff) {
                    float q = fmaf(Dd, act, hadd2(y2)) * zsv;
                    qBase[(size_t)t * DI + lane] = __float2bfloat16(q);
                    qsum += q;
                }
            }
        } else {
#pragma unroll 2
            for (int tt = 0; tt < TILE; tt++) {
                float dtr = sBC[wid][tt][32];
                float act = sAct[wid][tt][lane];
                float zsv = sZs[wid][tt][lane];
                float pre = fmaf(dtr, dtw, dtb);
                float dt = (pre > 20.f) ? pre : __logf(1.f + __expf(pre));
                float bx = dt * act;
                float y = 0.f;
#pragma unroll
                for (int k = 0; k < 8; k++) {
                    float hlo, hhi;
                    up2(h2[k], hlo, hhi);
                    float Blo = sBC[wid][tt][2 * k],     Bhi = sBC[wid][tt][2 * k + 1];
                    float Clo = sBC[wid][tt][16 + 2 * k], Chi = sBC[wid][tt][17 + 2 * k];
                    hlo = fmaf(__expf(dt * g_A[lane * DS + 2 * k]),     hlo, bx * Blo);
                    hhi = fmaf(__expf(dt * g_A[lane * DS + 2 * k + 1]), hhi, bx * Bhi);
                    y = fmaf(hlo, Clo, y);
                    y = fmaf(hhi, Chi, y);
                    h2[k] = pk2(hlo, hhi);
                }
                int t = tb + tt;
                if (t >= woff) {
                    float q = fmaf(Dd, act, y) * zsv;
                    qBase[(size_t)t * DI + lane] = __float2bfloat16(q);
                    qsum += q;
                }
            }
        }
        __syncwarp();
    }
    g_qpart[(s * NCH + ch) * DI + lane] = qsum;
}

// ---------------- SE gate ----------------------------------------------------
__global__ void k_se(const float* __restrict__ se_w1, const float* __restrict__ se_w2,
                     const float* __restrict__ out_w, const float* __restrict__ skip) {
    int s = threadIdx.x;
    if (s >= NSEQ) return;
    float qs[DI];
#pragma unroll 4
    for (int d = 0; d < DI; d++) {
        float a = 0.f;
        for (int ch = 0; ch < NCH; ch++) a += g_qpart[(s * NCH + ch) * DI + d];
        qs[d] = a * (1.f / (float)LSEQ);
    }
    float avg[32];
    for (int j = 0; j < 16; j++) {
        float m = 0.f;
        for (int d = 0; d < DI; d++) m = fmaf(qs[d], out_w[j * DI + d], m);
        avg[j] = m;
    }
    float sk = skip[0];
    for (int j = 0; j < 16; j++)
        avg[16 + j] = sk * g_unsum[s * 16 + j] * (1.f / (float)LSEQ);
    float t1[2];
    for (int i = 0; i < 2; i++) {
        float a = 0.f;
        for (int k = 0; k < 32; k++) a = fmaf(avg[k], se_w1[i * 32 + k], a);
        t1[i] = fmaxf(a, 0.f);
    }
    for (int k = 0; k < 32; k++) {
        float a = fmaf(t1[0], se_w2[k * 2 + 0], t1[1] * se_w2[k * 2 + 1]);
        g_gate[s * 32 + k] = sigf(a);
    }
}

// ---------------- pass 3: out-proj + gate + LN + 48-proj + transpose ---------
__global__ void __launch_bounds__(128) k_out(
    const float* __restrict__ ng, const float* __restrict__ nb,
    const float* __restrict__ proj_w, const float* __restrict__ proj_b,
    const float* __restrict__ out_w, const float* __restrict__ skip,
    float* __restrict__ out)
{
    __shared__ __align__(16) float sOW[DM][DI];
    __shared__ __align__(16) float sPW[COUT][CCH];
    __shared__ float sPB[COUT];
    __shared__ float sG1[4][16], sG2[4][16];
    int t = threadIdx.x, blk = blockIdx.x, b = blockIdx.y;
    for (int i = t; i < DM * DI; i += 128) sOW[i >> 5][i & 31] = out_w[i];
    for (int i = t; i < COUT * CCH; i += 128) {
        int o = i >> 6, c = i & 63;
        sPW[o][c] = proj_w[i] * ng[c];
    }
    if (t < COUT) {
        float a = proj_b[t];
        for (int c = 0; c < CCH; c++) a = fmaf(nb[c], proj_w[t * CCH + c], a);
        sPB[t] = a;
    }
    if (t < 64) {
        int g = t >> 4, j = t & 15, s = g * 16 + b;
        sG1[g][j] = g_gate[s * 32 + j];
        sG2[g][j] = g_gate[s * 32 + 16 + j] * skip[0];
    }
    __syncthreads();

    int l = blk * 128 + t;
    float ocs[CCH];
#pragma unroll
    for (int g = 0; g < 4; g++) {
        int s = g * 16 + b;
        // q (bf16, 32 values) -> 16 packed f32x2 pairs
        const __nv_bfloat162* qh =
            (const __nv_bfloat162*)(g_q + ((size_t)s * LSEQ + l) * DI);
        f2 q2[16];
#pragma unroll
        for (int i = 0; i < 16; i++) {
            float2 f = __bfloat1622float2(qh[i]);
            q2[i] = pk2(f.x, f.y);
        }
        const float4* u4 = (const float4*)(g_un + ((size_t)s * LSEQ + l) * DM);
        float uv[16];
#pragma unroll
        for (int i = 0; i < 4; i++) {
            float4 f = u4[i];
            uv[4 * i + 0] = f.x; uv[4 * i + 1] = f.y;
            uv[4 * i + 2] = f.z; uv[4 * i + 3] = f.w;
        }
#pragma unroll
        for (int j = 0; j < 16; j++) {
            const ulonglong2* wp = (const ulonglong2*)sOW[j];
            f2 m2 = 0ULL;
#pragma unroll
            for (int i = 0; i < 8; i++) {
                ulonglong2 w = wp[i];
                m2 = fma2(q2[2 * i], w.x, m2);
                m2 = fma2(q2[2 * i + 1], w.y, m2);
            }
            ocs[g * 16 + j] = fmaf(sG1[g][j], hadd2(m2), sG2[g][j] * uv[j]);
        }
    }
    // LN over 64 channels (packed)
    f2 oc2[32];
#pragma unroll
    for (int p = 0; p < 32; p++) oc2[p] = pk2(ocs[2 * p], ocs[2 * p + 1]);
    f2 s2 = 0ULL, v2 = 0ULL;
#pragma unroll
    for (int p = 0; p < 32; p++) {
        s2 = add2(s2, oc2[p]);
        v2 = fma2(oc2[p], oc2[p], v2);
    }
    float mean = hadd2(s2) * (1.f / 64.f);
    float rs = rsqrtf(hadd2(v2) * (1.f / 64.f) - mean * mean + 1e-5f);
    f2 rs2 = pk2(rs, rs);
    f2 mb2 = pk2(-mean * rs, -mean * rs);
#pragma unroll
    for (int p = 0; p < 32; p++) oc2[p] = fma2(oc2[p], rs2, mb2);

    float* ob = out + (size_t)b * COUT * LSEQ + l;
#pragma unroll 2
    for (int o = 0; o < COUT; o++) {
        const ulonglong2* wp = (const ulonglong2*)sPW[o];
        f2 acc2 = 0ULL;
#pragma unroll
        for (int i = 0; i < 16; i++) {
            ulonglong2 w = wp[i];
            acc2 = fma2(oc2[2 * i], w.x, acc2);
            acc2 = fma2(oc2[2 * i + 1], w.y, acc2);
        }
        ob[(size_t)o * LSEQ] = hadd2(acc2) + sPB[o];
    }
}

// ---------------- launch ------------------------------------------------------
extern "C" void kernel_launch(void* const* d_in, const int* in_sizes, int n_in,
                              void* d_out, int out_size) {
    (void)in_sizes; (void)n_in; (void)out_size;
    const float* x        = (const float*)d_in[0];
    const float* norm_g   = (const float*)d_in[1];
    const float* norm_b   = (const float*)d_in[2];
    const float* skip     = (const float*)d_in[3];
    const float* se_w1    = (const float*)d_in[4];
    const float* se_w2    = (const float*)d_in[5];
    const float* proj_w   = (const float*)d_in[6];
    const float* proj_b   = (const float*)d_in[7];
    const float* in_w     = (const float*)d_in[8];
    const float* conv_w   = (const float*)d_in[9];
    const float* conv_b   = (const float*)d_in[10];
    const float* xproj_w  = (const float*)d_in[11];
    const float* dtproj_w = (const float*)d_in[12];
    const float* dtproj_b = (const float*)d_in[13];
    const float* A_log    = (const float*)d_in[14];
    const float* Dp       = (const float*)d_in[15];
    const float* out_w    = (const float*)d_in[16];
    float* out = (float*)d_out;

    k_prep<<<1, 32>>>(A_log);
    k_ln1<<<dim3(NB1, BSZ), 128>>>(x, norm_g, norm_b);
    k_red1<<<4, 256>>>();
    k_scan<<<NSEQ * NCH / WPB, 128>>>(in_w, conv_w, conv_b, xproj_w,
                                      dtproj_w, dtproj_b, Dp);
    k_se<<<1, 64>>>(se_w1, se_w2, out_w, skip);
    k_out<<<dim3(NB1, BSZ), 128>>>(norm_g, norm_b, proj_w, proj_b, out_w,
                                   skip, out);
}

// round 17
// speedup vs baseline: 1.6305x; 1.6305x over previous
#include <cuda_runtime.h>
#include <cuda_bf16.h>
#include <cstdint>

#define BSZ  16
#define CCH  64
#define LSEQ 36864
#define DM   16
#define DI   32
#define DS   16
#define NSEQ 64
#define COUT 48

#define NCH  36
#define CSZ  1024          // LSEQ / NCH
#define WARM 32
#define TILE 16
#define WPB  4
#define NB1  288           // LSEQ / 128

// ---------------- packed f32x2 helpers (sm_103a; ptxas won't auto-fuse) ------
typedef unsigned long long f2;
__device__ __forceinline__ f2 pk2(float lo, float hi) {
    f2 r; asm("mov.b64 %0,{%1,%2};" : "=l"(r) : "f"(lo), "f"(hi)); return r;
}
__device__ __forceinline__ void up2(f2 v, float& a, float& b) {
    asm("mov.b64 {%0,%1},%2;" : "=f"(a), "=f"(b) : "l"(v));
}
__device__ __forceinline__ f2 fma2(f2 a, f2 b, f2 c) {
    f2 d; asm("fma.rn.f32x2 %0,%1,%2,%3;" : "=l"(d) : "l"(a), "l"(b), "l"(c)); return d;
}
__device__ __forceinline__ f2 mul2(f2 a, f2 b) {
    f2 d; asm("mul.rn.f32x2 %0,%1,%2;" : "=l"(d) : "l"(a), "l"(b)); return d;
}
__device__ __forceinline__ f2 add2(f2 a, f2 b) {
    f2 d; asm("add.rn.f32x2 %0,%1,%2;" : "=l"(d) : "l"(a), "l"(b)); return d;
}
__device__ __forceinline__ float hadd2(f2 v) {
    float a, b; up2(v, a, b); return a + b;
}

// ---------------- scratch (device globals; no runtime allocation) ------------
__device__ float         g_un[(size_t)NSEQ * LSEQ * DM];
__device__ __nv_bfloat16 g_q [(size_t)NSEQ * LSEQ * DI];
__device__ float g_unpart[BSZ * NB1 * CCH];
__device__ float g_qpart [NSEQ * NCH * DI];
__device__ float g_unsum [NSEQ * DM];
__device__ float g_gate  [NSEQ * DI];
__device__ float g_A [DI * DS];
__device__ float g_a0[DI];
__device__ int   g_struct;

__device__ __forceinline__ float sigf(float v) {
    return __fdividef(1.f, 1.f + __expf(-v));
}

// ---------------- prep: A = -exp(A_log), detect power structure --------------
__global__ void k_prep(const float* __restrict__ A_log) {
    int d = threadIdx.x;  // 32 threads
    float a[DS];
#pragma unroll
    for (int n = 0; n < DS; n++) {
        a[n] = -expf(A_log[d * DS + n]);
        g_A[d * DS + n] = a[n];
    }
    g_a0[d] = a[0];
    int good = 1;
#pragma unroll
    for (int n = 0; n < DS; n++) {
        float r = a[0] * (float)(n + 1);
        if (fabsf(a[n] - r) > 1e-4f * fmaxf(1.f, fabsf(r))) good = 0;
    }
    int allok = __syncthreads_and(good);
    if (d == 0) g_struct = allok;
}

// ---------------- pass 1: layernorm + regroup + skip partial sums ------------
__global__ void __launch_bounds__(128) k_ln1(const float* __restrict__ x,
                                             const float* __restrict__ ng,
                                             const float* __restrict__ nb) {
    __shared__ float tile[CCH][129];
    __shared__ float sM[128], sR[128];
    __shared__ float sG[CCH], sB[CCH];
    int t = threadIdx.x, blk = blockIdx.x, b = blockIdx.y;
    if (t < CCH) { sG[t] = ng[t]; sB[t] = nb[t]; }

    const float* xb = x + (size_t)b * CCH * LSEQ + (size_t)blk * 128;
    float sum = 0.f, sq = 0.f;
#pragma unroll 4
    for (int c = 0; c < CCH; c++) {
        float v = xb[(size_t)c * LSEQ + t];
        tile[c][t] = v;
        sum += v;
        sq = fmaf(v, v, sq);
    }
    float mean = sum * (1.f / 64.f);
    float var  = sq * (1.f / 64.f) - mean * mean;
    sM[t] = mean;
    sR[t] = rsqrtf(var + 1e-5f);
    __syncthreads();

#pragma unroll
    for (int g = 0; g < 4; g++) {
        float* ob = g_un + ((size_t)(g * 16 + b) * LSEQ + (size_t)blk * 128) * DM;
#pragma unroll 4
        for (int rep = 0; rep < 16; rep++) {
            int idx = rep * 128 + t;
            int l = idx >> 4, j = idx & 15;
            int c = g * 16 + j;
            ob[idx] = (tile[c][l] - sM[l]) * sR[l] * sG[c] + sB[c];
        }
    }
    if (t < CCH) {
        float a = 0.f;
#pragma unroll 4
        for (int l = 0; l < 128; l++) a += (tile[t][l] - sM[l]) * sR[l];
        g_unpart[((size_t)b * NB1 + blk) * CCH + t] = a * sG[t] + 128.f * sB[t];
    }
}

// ---------------- reduce skip-path partials ----------------------------------
__global__ void k_red1() {
    int id = blockIdx.x * 256 + threadIdx.x;
    if (id >= NSEQ * DM) return;
    int s = id >> 4, j = id & 15;
    int b = s & 15, g = s >> 4;
    float a = 0.f;
    for (int blk = 0; blk < NB1; blk++)
        a += g_unpart[((size_t)b * NB1 + blk) * CCH + g * 16 + j];
    g_unsum[id] = a;
}

// ---------------- pass 2: mamba (in-proj + conv + xproj + selective scan) ----
__global__ void __launch_bounds__(128, 4) k_scan(
    const float* __restrict__ in_w,     const float* __restrict__ conv_w,
    const float* __restrict__ conv_b,   const float* __restrict__ xproj_w,
    const float* __restrict__ dtproj_w, const float* __restrict__ dtproj_b,
    const float* __restrict__ Dp)
{
    __shared__ __align__(16) float w0s[32];               // xproj_w row 0
    __shared__ __align__(16) float su  [WPB][256];        // u tile [t][k]
    __shared__ __align__(16) float sAct[WPB][TILE][40];   // act [t][d]
    __shared__ __align__(16) float sZs [WPB][TILE][40];   // silu(z) [t][d]
    __shared__ __align__(16) float sBC [WPB][TILE][40];   // [0..15]=B [16..31]=C [32]=dt

    int tid = threadIdx.x, wid = tid >> 5, lane = tid & 31;
    if (tid < 32) w0s[tid] = xproj_w[tid];
    __syncthreads();

    int job = blockIdx.x * WPB + wid;          // 0..2303
    int s = job / NCH, ch = job - s * NCH;
    int qstart = ch * CSZ;
    int start  = (qstart >= WARM) ? (qstart - WARM) : 0;
    int nsteps = qstart + CSZ - start;
    int woff   = qstart - start;
    const float* uBase = g_un + ((size_t)s * LSEQ + start) * DM;
    __nv_bfloat16* qBase = g_q + ((size_t)s * LSEQ + start) * DI;

    // per-lane register-resident weights (packed pairs)
    f2 wx2[8], wz2[8], wc2[16];
    {
        const ulonglong2* wxp = (const ulonglong2*)(in_w + lane * 16);
        const ulonglong2* wzp = (const ulonglong2*)(in_w + (32 + lane) * 16);
        const ulonglong2* wcp = (const ulonglong2*)(xproj_w + 32 + lane * 32);
#pragma unroll
        for (int i = 0; i < 4; i++) {
            ulonglong2 a = wxp[i]; wx2[2 * i] = a.x; wx2[2 * i + 1] = a.y;
            ulonglong2 b = wzp[i]; wz2[2 * i] = b.x; wz2[2 * i + 1] = b.y;
        }
#pragma unroll
        for (int i = 0; i < 8; i++) {
            ulonglong2 c = wcp[i]; wc2[2 * i] = c.x; wc2[2 * i + 1] = c.y;
        }
    }
    float4 cwv = *(const float4*)(conv_w + lane * 4);
    float cb  = conv_b[lane];
    float dtw = dtproj_w[lane], dtb = dtproj_b[lane];
    float Dd  = Dp[lane], a0 = g_a0[lane];
    int structured = g_struct;

    f2 h2[8];
#pragma unroll
    for (int k = 0; k < 8; k++) h2[k] = 0ULL;
    float xm1 = 0.f, xm2 = 0.f, xm3 = 0.f;
    float qsum = 0.f;

    for (int tb = 0; tb < nsteps; tb += TILE) {
        // ---- A0: stage u tile ----
        {
            const float4* gsrc = (const float4*)(uBase + (size_t)tb * DM);
            float4* sdst = (float4*)su[wid];
            sdst[lane]      = gsrc[lane];
            sdst[lane + 32] = gsrc[lane + 32];
        }
        __syncwarp();

        // ---- A1: in-proj (packed k-pairs) + depthwise conv + silu (lane=d) --
#pragma unroll
        for (int t = 0; t < TILE; t++) {
            const ulonglong2* up = (const ulonglong2*)&su[wid][t * 16];
            ulonglong2 u0 = up[0], u1 = up[1], u2v = up[2], u3v = up[3];
            f2 ax2 = 0ULL, az2 = 0ULL;
            ax2 = fma2(u0.x, wx2[0], ax2);  az2 = fma2(u0.x, wz2[0], az2);
            ax2 = fma2(u0.y, wx2[1], ax2);  az2 = fma2(u0.y, wz2[1], az2);
            ax2 = fma2(u1.x, wx2[2], ax2);  az2 = fma2(u1.x, wz2[2], az2);
            ax2 = fma2(u1.y, wx2[3], ax2);  az2 = fma2(u1.y, wz2[3], az2);
            ax2 = fma2(u2v.x, wx2[4], ax2); az2 = fma2(u2v.x, wz2[4], az2);
            ax2 = fma2(u2v.y, wx2[5], ax2); az2 = fma2(u2v.y, wz2[5], az2);
            ax2 = fma2(u3v.x, wx2[6], ax2); az2 = fma2(u3v.x, wz2[6], az2);
            ax2 = fma2(u3v.y, wx2[7], ax2); az2 = fma2(u3v.y, wz2[7], az2);
            float ax = hadd2(ax2), az = hadd2(az2);
            float acc = cb;
            acc = fmaf(cwv.x, xm3, acc);
            acc = fmaf(cwv.y, xm2, acc);
            acc = fmaf(cwv.z, xm1, acc);
            acc = fmaf(cwv.w, ax,  acc);
            xm3 = xm2; xm2 = xm1; xm1 = ax;
            sAct[wid][t][lane] = acc * sigf(acc);
            sZs [wid][t][lane] = az * sigf(az);
        }
        __syncwarp();

        // ---- A3: x-projection (lane = output column, packed d-pairs) --------
        {
#pragma unroll
            for (int t = 0; t < TILE; t++) {
                const ulonglong2* ap = (const ulonglong2*)&sAct[wid][t][0];
                f2 o2 = 0ULL;
#pragma unroll
                for (int i = 0; i < 8; i++) {
                    ulonglong2 a = ap[i];
                    o2 = fma2(a.x, wc2[2 * i], o2);
                    o2 = fma2(a.y, wc2[2 * i + 1], o2);
                }
                sBC[wid][t][lane] = hadd2(o2);
            }
            // dt_raw row: lanes 0..15 each handle one timestep
            if (lane < TILE) {
                const ulonglong2* ap = (const ulonglong2*)&sAct[wid][lane][0];
                const ulonglong2* wp = (const ulonglong2*)w0s;
                f2 s2 = 0ULL;
#pragma unroll
                for (int i = 0; i < 8; i++) {
                    ulonglong2 a = ap[i];
                    ulonglong2 w = wp[i];
                    s2 = fma2(a.x, w.x, s2);
                    s2 = fma2(a.y, w.y, s2);
                }
                sBC[wid][lane][32] = hadd2(s2);
            }
        }
        __syncwarp();

        // ---- B: selective scan (lane = d, packed n-pairs) -------------------
        if (structured) {
#pragma unroll
            for (int tt = 0; tt < TILE; tt++) {
                float dtr = sBC[wid][tt][32];
                float act = sAct[wid][tt][lane];
                float zsv = sZs[wid][tt][lane];
                float pre = fmaf(dtr, dtw, dtb);
                float dt = (pre > 20.f) ? pre : __logf(1.f + __expf(pre));
                float bx = dt * act;
                f2 bx2 = pk2(bx, bx);
                float p = __expf(dt * a0);
                float pq = p * p;
                f2 Q = pk2(pq, pq);
                f2 pw = pk2(p, pq);
                const ulonglong2* bp = (const ulonglong2*)&sBC[wid][tt][0];
                ulonglong2 Bq0 = bp[0], Bq1 = bp[1], Bq2 = bp[2], Bq3 = bp[3];
                ulonglong2 Cq0 = bp[4], Cq1 = bp[5], Cq2 = bp[6], Cq3 = bp[7];
                f2 Bv[8] = {Bq0.x, Bq0.y, Bq1.x, Bq1.y, Bq2.x, Bq2.y, Bq3.x, Bq3.y};
                f2 Cv[8] = {Cq0.x, Cq0.y, Cq1.x, Cq1.y, Cq2.x, Cq2.y, Cq3.x, Cq3.y};
                f2 y2 = 0ULL;
#pragma unroll
                for (int k = 0; k < 8; k++) {
                    h2[k] = fma2(pw, h2[k], mul2(bx2, Bv[k]));
                    y2 = fma2(h2[k], Cv[k], y2);
                    pw = mul2(pw, Q);
                }
                int t = tb + tt;
                if (t >= woff) {
                    float q = fmaf(Dd, act, hadd2(y2)) * zsv;
                    qBase[(size_t)t * DI + lane] = __float2bfloat16(q);
                    qsum += q;
                }
            }
        } else {
#pragma unroll 2
            for (int tt = 0; tt < TILE; tt++) {
                float dtr = sBC[wid][tt][32];
                float act = sAct[wid][tt][lane];
                float zsv = sZs[wid][tt][lane];
                float pre = fmaf(dtr, dtw, dtb);
                float dt = (pre > 20.f) ? pre : __logf(1.f + __expf(pre));
                float bx = dt * act;
                float y = 0.f;
#pragma unroll
                for (int k = 0; k < 8; k++) {
                    float hlo, hhi;
                    up2(h2[k], hlo, hhi);
                    float Blo = sBC[wid][tt][2 * k],     Bhi = sBC[wid][tt][2 * k + 1];
                    float Clo = sBC[wid][tt][16 + 2 * k], Chi = sBC[wid][tt][17 + 2 * k];
                    hlo = fmaf(__expf(dt * g_A[lane * DS + 2 * k]),     hlo, bx * Blo);
                    hhi = fmaf(__expf(dt * g_A[lane * DS + 2 * k + 1]), hhi, bx * Bhi);
                    y = fmaf(hlo, Clo, y);
                    y = fmaf(hhi, Chi, y);
                    h2[k] = pk2(hlo, hhi);
                }
                int t = tb + tt;
                if (t >= woff) {
                    float q = fmaf(Dd, act, y) * zsv;
                    qBase[(size_t)t * DI + lane] = __float2bfloat16(q);
                    qsum += q;
                }
            }
        }
        __syncwarp();
    }
    g_qpart[(s * NCH + ch) * DI + lane] = qsum;
}

// ---------------- SE gate ----------------------------------------------------
__global__ void k_se(const float* __restrict__ se_w1, const float* __restrict__ se_w2,
                     const float* __restrict__ out_w, const float* __restrict__ skip) {
    int s = threadIdx.x;
    if (s >= NSEQ) return;
    float qs[DI];
#pragma unroll 4
    for (int d = 0; d < DI; d++) {
        float a = 0.f;
        for (int ch = 0; ch < NCH; ch++) a += g_qpart[(s * NCH + ch) * DI + d];
        qs[d] = a * (1.f / (float)LSEQ);
    }
    float avg[32];
    for (int j = 0; j < 16; j++) {
        float m = 0.f;
        for (int d = 0; d < DI; d++) m = fmaf(qs[d], out_w[j * DI + d], m);
        avg[j] = m;
    }
    float sk = skip[0];
    for (int j = 0; j < 16; j++)
        avg[16 + j] = sk * g_unsum[s * 16 + j] * (1.f / (float)LSEQ);
    float t1[2];
    for (int i = 0; i < 2; i++) {
        float a = 0.f;
        for (int k = 0; k < 32; k++) a = fmaf(avg[k], se_w1[i * 32 + k], a);
        t1[i] = fmaxf(a, 0.f);
    }
    for (int k = 0; k < 32; k++) {
        float a = fmaf(t1[0], se_w2[k * 2 + 0], t1[1] * se_w2[k * 2 + 1]);
        g_gate[s * 32 + k] = sigf(a);
    }
}

// ---------------- pass 3: out-proj + gate + LN + 48-proj + transpose ---------
__global__ void __launch_bounds__(128) k_out(
    const float* __restrict__ ng, const float* __restrict__ nb,
    const float* __restrict__ proj_w, const float* __restrict__ proj_b,
    const float* __restrict__ out_w, const float* __restrict__ skip,
    float* __restrict__ out)
{
    __shared__ __align__(16) float sOW[DM][DI];
    __shared__ __align__(16) float sPW[COUT][CCH];
    __shared__ float sPB[COUT];
    __shared__ float sG1[4][16], sG2[4][16];
    int t = threadIdx.x, blk = blockIdx.x, b = blockIdx.y;
    for (int i = t; i < DM * DI; i += 128) sOW[i >> 5][i & 31] = out_w[i];
    for (int i = t; i < COUT * CCH; i += 128) {
        int o = i >> 6, c = i & 63;
        sPW[o][c] = proj_w[i] * ng[c];
    }
    if (t < COUT) {
        float a = proj_b[t];
        for (int c = 0; c < CCH; c++) a = fmaf(nb[c], proj_w[t * CCH + c], a);
        sPB[t] = a;
    }
    if (t < 64) {
        int g = t >> 4, j = t & 15, s = g * 16 + b;
        sG1[g][j] = g_gate[s * 32 + j];
        sG2[g][j] = g_gate[s * 32 + 16 + j] * skip[0];
    }
    __syncthreads();

    int l = blk * 128 + t;
    // LN inputs packed directly into pairs (never materialize a 64-float array)
    f2 oc2[32];
#pragma unroll
    for (int g = 0; g < 4; g++) {
        int s = g * 16 + b;
        // q (bf16, 32 values) -> 16 packed f32x2 pairs (live only inside this g)
        const __nv_bfloat162* qh =
            (const __nv_bfloat162*)(g_q + ((size_t)s * LSEQ + l) * DI);
        f2 q2[16];
#pragma unroll
        for (int i = 0; i < 16; i++) {
            float2 f = __bfloat1622float2(qh[i]);
            q2[i] = pk2(f.x, f.y);
        }
        const float4* u4 = (const float4*)(g_un + ((size_t)s * LSEQ + l) * DM);
        float uv[16];
#pragma unroll
        for (int i = 0; i < 4; i++) {
            float4 f = u4[i];
            uv[4 * i + 0] = f.x; uv[4 * i + 1] = f.y;
            uv[4 * i + 2] = f.z; uv[4 * i + 3] = f.w;
        }
        float mlo = 0.f;
#pragma unroll
        for (int j = 0; j < 16; j++) {
            const ulonglong2* wp = (const ulonglong2*)sOW[j];
            f2 m2 = 0ULL;
#pragma unroll
            for (int i = 0; i < 8; i++) {
                ulonglong2 w = wp[i];
                m2 = fma2(q2[2 * i], w.x, m2);
                m2 = fma2(q2[2 * i + 1], w.y, m2);
            }
            float mj = fmaf(sG1[g][j], hadd2(m2), sG2[g][j] * uv[j]);
            if ((j & 1) == 0) {
                mlo = mj;
            } else {
                oc2[(g * 16 + j) >> 1] = pk2(mlo, mj);
            }
        }
    }
    // LN over 64 channels (packed)
    f2 s2 = 0ULL, v2 = 0ULL;
#pragma unroll
    for (int p = 0; p < 32; p++) {
        s2 = add2(s2, oc2[p]);
        v2 = fma2(oc2[p], oc2[p], v2);
    }
    float mean = hadd2(s2) * (1.f / 64.f);
    float rs = rsqrtf(hadd2(v2) * (1.f / 64.f) - mean * mean + 1e-5f);
    f2 rs2 = pk2(rs, rs);
    f2 mb2 = pk2(-mean * rs, -mean * rs);
#pragma unroll
    for (int p = 0; p < 32; p++) oc2[p] = fma2(oc2[p], rs2, mb2);

    float* ob = out + (size_t)b * COUT * LSEQ + l;
#pragma unroll 2
    for (int o = 0; o < COUT; o++) {
        const ulonglong2* wp = (const ulonglong2*)sPW[o];
        f2 acc2 = 0ULL;
#pragma unroll
        for (int i = 0; i < 16; i++) {
            ulonglong2 w = wp[i];
            acc2 = fma2(oc2[2 * i], w.x, acc2);
            acc2 = fma2(oc2[2 * i + 1], w.y, acc2);
        }
        ob[(size_t)o * LSEQ] = hadd2(acc2) + sPB[o];
    }
}

// ---------------- launch ------------------------------------------------------
extern "C" void kernel_launch(void* const* d_in, const int* in_sizes, int n_in,
                              void* d_out, int out_size) {
    (void)in_sizes; (void)n_in; (void)out_size;
    const float* x        = (const float*)d_in[0];
    const float* norm_g   = (const float*)d_in[1];
    const float* norm_b   = (const float*)d_in[2];
    const float* skip     = (const float*)d_in[3];
    const float* se_w1    = (const float*)d_in[4];
    const float* se_w2    = (const float*)d_in[5];
    const float* proj_w   = (const float*)d_in[6];
    const float* proj_b   = (const float*)d_in[7];
    const float* in_w     = (const float*)d_in[8];
    const float* conv_w   = (const float*)d_in[9];
    const float* conv_b   = (const float*)d_in[10];
    const float* xproj_w  = (const float*)d_in[11];
    const float* dtproj_w = (const float*)d_in[12];
    const float* dtproj_b = (const float*)d_in[13];
    const float* A_log    = (const float*)d_in[14];
    const float* Dp       = (const float*)d_in[15];
    const float* out_w    = (const float*)d_in[16];
    float* out = (float*)d_out;

    k_prep<<<1, 32>>>(A_log);
    k_ln1<<<dim3(NB1, BSZ), 128>>>(x, norm_g, norm_b);
    k_red1<<<4, 256>>>();
    k_scan<<<NSEQ * NCH / WPB, 128>>>(in_w, conv_w, conv_b, xproj_w,
                                      dtproj_w, dtproj_b, Dp);
    k_se<<<1, 64>>>(se_w1, se_w2, out_w, skip);
    k_out<<<dim3(NB1, BSZ), 128>>>(norm_g, norm_b, proj_w, proj_b, out_w,
                                   skip, out);
}